// round 5
// baseline (speedup 1.0000x reference)
#include <cuda_runtime.h>
#include <cuda_fp16.h>
#include <math.h>
#include <stdint.h>

#define N_TOK    16384
#define HID      4096
#define NE       64
#define TM       128
#define KT       64                  // K-tile (fp32 elements)
#define NKT      (HID/KT)            // 64
#define NTHREADS 512
#define NBLK     (N_TOK/TM)          // 128

// smem: padded half rows, stride 72 halves = 144 B
#define SM_RED    0
#define BUF0      1024
#define OFF_AHI   0
#define OFF_ALO   18432              // 128*144
#define OFF_BHI   36864
#define OFF_BLO   46080
#define BUF_BYTES 55296
#define SMEM_TOTAL (BUF0 + 2*BUF_BYTES)   // 111616
#define LS_OFF    BUF0               // epilogue logits 128 x 65 fp32

// per-block partials + arrival counter (single fused kernel, no zero/finalize launches)
__device__ float g_Pp[NBLK * NE];
__device__ float g_cp[NBLK * NE];
__device__ float g_zp[NBLK];
__device__ unsigned int g_arrive = 0;

__device__ __forceinline__ uint32_t smem_u32(const void* p) {
    uint32_t a;
    asm("{ .reg .u64 t; cvta.to.shared.u64 t, %1; cvt.u32.u64 %0, t; }" : "=r"(a) : "l"(p));
    return a;
}
__device__ __forceinline__ void mma16816(float* c, const uint32_t* a, const uint32_t* b) {
    asm volatile(
        "mma.sync.aligned.m16n8k16.row.col.f32.f16.f16.f32 "
        "{%0,%1,%2,%3}, {%4,%5,%6,%7}, {%8,%9}, {%0,%1,%2,%3};"
        : "+f"(c[0]), "+f"(c[1]), "+f"(c[2]), "+f"(c[3])
        : "r"(a[0]), "r"(a[1]), "r"(a[2]), "r"(a[3]), "r"(b[0]), "r"(b[1]));
}
#define LDSM4(r, addr)                                                        \
    asm volatile("ldmatrix.sync.aligned.m8n8.x4.shared.b16 {%0,%1,%2,%3}, [%4];" \
        : "=r"((r)[0]), "=r"((r)[1]), "=r"((r)[2]), "=r"((r)[3]) : "r"(addr))

__device__ __forceinline__ void split4(float4 v, uint2& hi, uint2& lo) {
    __half2 h01 = __floats2half2_rn(v.x, v.y);
    __half2 h23 = __floats2half2_rn(v.z, v.w);
    float2 f01 = __half22float2(h01);
    float2 f23 = __half22float2(h23);
    __half2 l01 = __floats2half2_rn(v.x - f01.x, v.y - f01.y);
    __half2 l23 = __floats2half2_rn(v.z - f23.x, v.w - f23.y);
    hi.x = *reinterpret_cast<uint32_t*>(&h01);
    hi.y = *reinterpret_cast<uint32_t*>(&h23);
    lo.x = *reinterpret_cast<uint32_t*>(&l01);
    lo.y = *reinterpret_cast<uint32_t*>(&l23);
}

__global__ void __launch_bounds__(NTHREADS, 1)
router_fused(const float* __restrict__ X, const float* __restrict__ Wg,
             float* __restrict__ out)
{
    extern __shared__ char smem[];
    const uint32_t sb = smem_u32(smem);
    const int tid  = threadIdx.x;
    const int lane = tid & 31;
    const int wid  = tid >> 5;
    const int bid  = blockIdx.x;
    const int t0   = bid * TM;
    const int mg   = (wid & 7) * 16;     // warp token base (16 tokens)
    const int ng   = (wid >> 3) * 32;    // warp expert base (32 experts)

    float* shp   = (float*)(smem + SM_RED);
    float* shcnt = shp + NE;
    float* shz   = shp + 2 * NE;
    if (tid < NE) { shp[tid] = 0.f; shcnt[tid] = 0.f; }
    if (tid == 0) shz[0] = 0.f;

    const float4* Xv = reinterpret_cast<const float4*>(X);
    const float4* Wv = reinterpret_cast<const float4*>(Wg);

    // staging: A 4 float4/thread (128 rows x 16 f4 = 2048), B 2 f4/thread (1024)
    int arow[4], ac4[4], brow[2], bc4[2];
#pragma unroll
    for (int i = 0; i < 4; i++) { int idx = tid + NTHREADS * i; arow[i] = idx >> 4; ac4[i] = idx & 15; }
#pragma unroll
    for (int i = 0; i < 2; i++) { int idx = tid + NTHREADS * i; brow[i] = idx >> 4; bc4[i] = idx & 15; }

    float4 stA[4], stB[2];

    auto LOAD = [&](int kt) {
#pragma unroll
        for (int i = 0; i < 4; i++)
            stA[i] = Xv[(size_t)(t0 + arow[i]) * (HID / 4) + kt * 16 + ac4[i]];
#pragma unroll
        for (int i = 0; i < 2; i++)
            stB[i] = Wv[(size_t)brow[i] * (HID / 4) + kt * 16 + bc4[i]];
    };

    auto STS = [&](int buf) {
        char* bp = smem + BUF0 + buf * BUF_BYTES;
        uint2* pAH = (uint2*)(bp + OFF_AHI);
        uint2* pAL = (uint2*)(bp + OFF_ALO);
        uint2* pBH = (uint2*)(bp + OFF_BHI);
        uint2* pBL = (uint2*)(bp + OFF_BLO);
#pragma unroll
        for (int i = 0; i < 4; i++) {
            uint2 h, l; split4(stA[i], h, l);
            int o = arow[i] * 18 + ac4[i];
            pAH[o] = h; pAL[o] = l;
        }
#pragma unroll
        for (int i = 0; i < 2; i++) {
            uint2 h, l; split4(stB[i], h, l);
            int o = brow[i] * 18 + bc4[i];
            pBH[o] = h; pBL[o] = l;
        }
    };

    float acc[4][4];
#pragma unroll
    for (int nt = 0; nt < 4; nt++)
#pragma unroll
        for (int k = 0; k < 4; k++) acc[nt][k] = 0.f;

    // ldmatrix per-lane byte offsets within a tile region
    const uint32_t aoff = (uint32_t)(mg + (lane & 15)) * 144 + ((lane >> 4) & 1) * 16;
    const int bmat = lane >> 3;                               // 0..3
    const uint32_t boff0 = (uint32_t)(ng + (bmat >> 1) * 8 + (lane & 7)) * 144 + (bmat & 1) * 16;
    const uint32_t boff1 = boff0 + 16 * 144;                  // experts +16

    auto COMPUTE = [&](int buf) {
        const uint32_t bb = sb + BUF0 + buf * BUF_BYTES;
        const uint32_t aH = bb + OFF_AHI + aoff;
        const uint32_t aL = bb + OFF_ALO + aoff;
        const uint32_t bH0 = bb + OFF_BHI + boff0;
        const uint32_t bH1 = bb + OFF_BHI + boff1;
        const uint32_t bL0 = bb + OFF_BLO + boff0;
        const uint32_t bL1 = bb + OFF_BLO + boff1;
#pragma unroll
        for (int kc = 0; kc < 4; kc++) {
            const uint32_t ko = kc * 32;
            uint32_t ah[4], al[4], bh[8], bl[8];
            LDSM4(ah, aH + ko);
            LDSM4(al, aL + ko);
            LDSM4(bh,     bH0 + ko);
            LDSM4(bh + 4, bH1 + ko);
            LDSM4(bl,     bL0 + ko);
            LDSM4(bl + 4, bL1 + ko);
            // pass-major: consecutive MMAs hit different accumulators (no RAW stalls)
#pragma unroll
            for (int nt = 0; nt < 4; nt++) mma16816(acc[nt], ah, bh + 2 * nt);
#pragma unroll
            for (int nt = 0; nt < 4; nt++) mma16816(acc[nt], ah, bl + 2 * nt);
#pragma unroll
            for (int nt = 0; nt < 4; nt++) mma16816(acc[nt], al, bh + 2 * nt);
        }
    };

    LOAD(0);
    STS(0);
    __syncthreads();
    for (int kt = 0; kt < NKT; kt++) {
        const int buf = kt & 1;
        if (kt + 1 < NKT) LOAD(kt + 1);
        COMPUTE(buf);
        if (kt + 1 < NKT) STS(buf ^ 1);
        __syncthreads();
    }

    // scatter accumulators to padded logits buffer [128][65]
    float* Ls = (float*)(smem + LS_OFF);
    {
        const int r = lane >> 2;
        const int c = 2 * (lane & 3);
#pragma unroll
        for (int nt = 0; nt < 4; nt++) {
            const int row = mg + r;
            const int col = ng + nt * 8 + c;
            Ls[row * 65 + col]           = acc[nt][0];
            Ls[row * 65 + col + 1]       = acc[nt][1];
            Ls[(row + 8) * 65 + col]     = acc[nt][2];
            Ls[(row + 8) * 65 + col + 1] = acc[nt][3];
        }
    }
    __syncthreads();

    // per-token epilogue on threads 0..127
    if (tid < TM) {
        const float* row = Ls + tid * 65;
        float l1 = -1e30f, l2 = -1e30f; int i1 = 0, i2 = 0;
#pragma unroll
        for (int e = 0; e < NE; e++) {
            const float v = row[e];
            if (v > l1)      { l2 = l1; i2 = i1; l1 = v; i1 = e; }
            else if (v > l2) { l2 = v; i2 = e; }
        }
        float s = 0.f;
#pragma unroll
        for (int e = 0; e < NE; e++) s += expf(row[e] - l1);
        const float inv_s = 1.f / s;
        const float lse   = l1 + logf(s);

        const float p2   = expf(l2 - l1);
        const float wsum = 1.f + p2;
        const int   gt   = t0 + tid;
        out[2 * gt]                 = 1.f / wsum;
        out[2 * gt + 1]             = p2 / wsum;
        out[2 * N_TOK + 2 * gt]     = (float)i1;
        out[2 * N_TOK + 2 * gt + 1] = (float)i2;

#pragma unroll
        for (int e = 0; e < NE; e++) {
            float v = expf(row[e] - l1) * inv_s;
#pragma unroll
            for (int o = 16; o > 0; o >>= 1) v += __shfl_xor_sync(0xffffffffu, v, o);
            if (lane == 0) atomicAdd(&shp[e], v);
        }
        atomicAdd(&shcnt[i1], 1.f);
        atomicAdd(&shcnt[i2], 1.f);
        float zv = lse * lse;
#pragma unroll
        for (int o = 16; o > 0; o >>= 1) zv += __shfl_xor_sync(0xffffffffu, zv, o);
        if (lane == 0) atomicAdd(shz, zv);
    }
    __syncthreads();

    // publish per-block partials
    if (tid < NE) {
        g_Pp[bid * NE + tid] = shp[tid];
        g_cp[bid * NE + tid] = shcnt[tid];
    }
    if (tid == 0) g_zp[bid] = shz[0];
    __threadfence();

    // last CTA to arrive does the global reduction (deterministic result)
    __shared__ unsigned int sLast;
    if (tid == 0) {
        unsigned int r = atomicAdd(&g_arrive, 1u);
        sLast = (r == (unsigned)(gridDim.x - 1)) ? 1u : 0u;
    }
    __syncthreads();
    if (sLast) {
        __threadfence();
        if (tid == 0) shz[0] = 0.f;
        __syncthreads();
        float fp = 0.f;
        if (tid < NE) {
            float sp = 0.f, sc = 0.f;
            for (int b = 0; b < NBLK; b++) {
                sp += g_Pp[b * NE + tid];
                sc += g_cp[b * NE + tid];
            }
            const float f = sc * (1.f / (N_TOK * 2.f));
            const float P = sp * (1.f / N_TOK);
            fp = f * P;
        }
        if (tid >= 128 && tid < 128 + NBLK)
            atomicAdd(shz, g_zp[tid - 128]);
        // reduce fp over threads 0..63 (warps 0,1)
        if (tid < NE) {
#pragma unroll
            for (int o = 16; o > 0; o >>= 1) fp += __shfl_xor_sync(0xffffffffu, fp, o);
            if (lane == 0) shp[wid] = fp;   // shp[0], shp[1]
        }
        __syncthreads();
        if (tid == 0) {
            const float lb = (float)NE * (shp[0] + shp[1]);
            const float z  = shz[0] * (1.f / N_TOK);
            out[4 * N_TOK] = 0.001f * lb + 0.001f * z;
            g_arrive = 0;   // reset for next graph replay
        }
    }
}

extern "C" void kernel_launch(void* const* d_in, const int* in_sizes, int n_in,
                              void* d_out, int out_size)
{
    (void)in_sizes; (void)n_in; (void)out_size;
    const float* X  = (const float*)d_in[0];
    const float* Wg = (const float*)d_in[1];
    float* out = (float*)d_out;

    cudaFuncSetAttribute(router_fused, cudaFuncAttributeMaxDynamicSharedMemorySize, SMEM_TOTAL);
    router_fused<<<NBLK, NTHREADS, SMEM_TOTAL>>>(X, Wg, out);
}

// round 6
// speedup vs baseline: 1.2476x; 1.2476x over previous
#include <cuda_runtime.h>
#include <cuda_fp16.h>
#include <math.h>
#include <stdint.h>

#define N_TOK    16384
#define HID      4096
#define NE       64
#define TM       128
#define KT       64                  // K-tile (fp32 elements)
#define NKT      (HID/KT)            // 64
#define NTHREADS 256
#define NBLK     (N_TOK/TM)          // 128

// smem: padded half rows, stride 72 halves = 144 B (conflict-free ldmatrix)
#define SM_RED    0
#define BUF0      1024
#define OFF_AHI   0
#define OFF_ALO   18432              // 128*144
#define OFF_BHI   36864
#define OFF_BLO   46080
#define BUF_BYTES 55296
#define SMEM_TOTAL (BUF0 + 2*BUF_BYTES)   // 111616
#define LS_OFF    BUF0               // epilogue logits 128 x 65 fp32

// per-block partials + arrival counter (fused single-kernel reduction)
__device__ float g_Pp[NBLK * NE];
__device__ float g_cp[NBLK * NE];
__device__ float g_zp[NBLK];
__device__ unsigned int g_arrive = 0;

__device__ __forceinline__ uint32_t smem_u32(const void* p) {
    uint32_t a;
    asm("{ .reg .u64 t; cvta.to.shared.u64 t, %1; cvt.u32.u64 %0, t; }" : "=r"(a) : "l"(p));
    return a;
}
__device__ __forceinline__ void mma16816(float* c, const uint32_t* a, const uint32_t* b) {
    asm volatile(
        "mma.sync.aligned.m16n8k16.row.col.f32.f16.f16.f32 "
        "{%0,%1,%2,%3}, {%4,%5,%6,%7}, {%8,%9}, {%0,%1,%2,%3};"
        : "+f"(c[0]), "+f"(c[1]), "+f"(c[2]), "+f"(c[3])
        : "r"(a[0]), "r"(a[1]), "r"(a[2]), "r"(a[3]), "r"(b[0]), "r"(b[1]));
}
#define LDSM4(r, addr)                                                           \
    asm volatile("ldmatrix.sync.aligned.m8n8.x4.shared.b16 {%0,%1,%2,%3}, [%4];" \
        : "=r"((r)[0]), "=r"((r)[1]), "=r"((r)[2]), "=r"((r)[3]) : "r"(addr))

__device__ __forceinline__ void split4(float4 v, uint2& hi, uint2& lo) {
    __half2 h01 = __floats2half2_rn(v.x, v.y);
    __half2 h23 = __floats2half2_rn(v.z, v.w);
    float2 f01 = __half22float2(h01);
    float2 f23 = __half22float2(h23);
    __half2 l01 = __floats2half2_rn(v.x - f01.x, v.y - f01.y);
    __half2 l23 = __floats2half2_rn(v.z - f23.x, v.w - f23.y);
    hi.x = *reinterpret_cast<uint32_t*>(&h01);
    hi.y = *reinterpret_cast<uint32_t*>(&h23);
    lo.x = *reinterpret_cast<uint32_t*>(&l01);
    lo.y = *reinterpret_cast<uint32_t*>(&l23);
}

__global__ void __launch_bounds__(NTHREADS, 1)
router_fused(const float* __restrict__ X, const float* __restrict__ Wg,
             float* __restrict__ out)
{
    extern __shared__ char smem[];
    const uint32_t sb = smem_u32(smem);
    const int tid  = threadIdx.x;
    const int lane = tid & 31;
    const int wid  = tid >> 5;
    const int bid  = blockIdx.x;
    const int t0   = bid * TM;
    const int mg   = (wid & 3) * 32;     // warp token base (32 tokens)
    const int ng   = (wid >> 2) * 32;    // warp expert base (32 experts)

    float* shp   = (float*)(smem + SM_RED);
    float* shcnt = shp + NE;
    float* shz   = shp + 2 * NE;
    if (tid < NE) { shp[tid] = 0.f; shcnt[tid] = 0.f; }
    if (tid == 0) shz[0] = 0.f;

    const float4* Xv = reinterpret_cast<const float4*>(X);
    const float4* Wv = reinterpret_cast<const float4*>(Wg);

    // staging: A 8 float4/thread (128 rows x 16 f4), B 4 f4/thread (64 x 16)
    int arow[8], ac4[8], brow[4], bc4[4];
#pragma unroll
    for (int i = 0; i < 8; i++) { int idx = tid + NTHREADS * i; arow[i] = idx >> 4; ac4[i] = idx & 15; }
#pragma unroll
    for (int i = 0; i < 4; i++) { int idx = tid + NTHREADS * i; brow[i] = idx >> 4; bc4[i] = idx & 15; }

    float4 stA[8], stB[4];

    auto LOAD = [&](int kt) {
#pragma unroll
        for (int i = 0; i < 8; i++)
            stA[i] = Xv[(size_t)(t0 + arow[i]) * (HID / 4) + kt * 16 + ac4[i]];
#pragma unroll
        for (int i = 0; i < 4; i++)
            stB[i] = Wv[(size_t)brow[i] * (HID / 4) + kt * 16 + bc4[i]];
    };

    auto STS = [&](int buf) {
        char* bp = smem + BUF0 + buf * BUF_BYTES;
        uint2* pAH = (uint2*)(bp + OFF_AHI);
        uint2* pAL = (uint2*)(bp + OFF_ALO);
        uint2* pBH = (uint2*)(bp + OFF_BHI);
        uint2* pBL = (uint2*)(bp + OFF_BLO);
#pragma unroll
        for (int i = 0; i < 8; i++) {
            uint2 h, l; split4(stA[i], h, l);
            int o = arow[i] * 18 + ac4[i];
            pAH[o] = h; pAL[o] = l;
        }
#pragma unroll
        for (int i = 0; i < 4; i++) {
            uint2 h, l; split4(stB[i], h, l);
            int o = brow[i] * 18 + bc4[i];
            pBH[o] = h; pBL[o] = l;
        }
    };

    float acc[2][4][4];
#pragma unroll
    for (int mt = 0; mt < 2; mt++)
#pragma unroll
        for (int nt = 0; nt < 4; nt++)
#pragma unroll
            for (int k = 0; k < 4; k++) acc[mt][nt][k] = 0.f;

    // ldmatrix per-lane byte offsets (validated fragment mappings from R5)
    const uint32_t aoff = (uint32_t)(mg + (lane & 15)) * 144 + ((lane >> 4) & 1) * 16;
    const int bmat = lane >> 3;                               // 0..3
    const uint32_t boff0 = (uint32_t)(ng + (bmat >> 1) * 8 + (lane & 7)) * 144 + (bmat & 1) * 16;
    const uint32_t boff1 = boff0 + 16 * 144;                  // experts +16

    auto COMPUTE = [&](int buf) {
        const uint32_t bb = sb + BUF0 + buf * BUF_BYTES;
        const uint32_t aH0 = bb + OFF_AHI + aoff;
        const uint32_t aH1 = aH0 + 16 * 144;                  // tokens +16
        const uint32_t aL0 = bb + OFF_ALO + aoff;
        const uint32_t aL1 = aL0 + 16 * 144;
        const uint32_t bH0 = bb + OFF_BHI + boff0;
        const uint32_t bH1 = bb + OFF_BHI + boff1;
        const uint32_t bL0 = bb + OFF_BLO + boff0;
        const uint32_t bL1 = bb + OFF_BLO + boff1;
#pragma unroll
        for (int kc = 0; kc < 4; kc++) {
            const uint32_t ko = kc * 32;
            uint32_t ah[8], al[8], bh[8], bl[8];
            LDSM4(ah,     aH0 + ko);
            LDSM4(ah + 4, aH1 + ko);
            LDSM4(al,     aL0 + ko);
            LDSM4(al + 4, aL1 + ko);
            LDSM4(bh,     bH0 + ko);
            LDSM4(bh + 4, bH1 + ko);
            LDSM4(bl,     bL0 + ko);
            LDSM4(bl + 4, bL1 + ko);
            // pass-major: 8 independent accumulators back-to-back per pass
#pragma unroll
            for (int mt = 0; mt < 2; mt++)
#pragma unroll
                for (int nt = 0; nt < 4; nt++)
                    mma16816(acc[mt][nt], ah + 4 * mt, bh + 2 * nt);
#pragma unroll
            for (int mt = 0; mt < 2; mt++)
#pragma unroll
                for (int nt = 0; nt < 4; nt++)
                    mma16816(acc[mt][nt], ah + 4 * mt, bl + 2 * nt);
#pragma unroll
            for (int mt = 0; mt < 2; mt++)
#pragma unroll
                for (int nt = 0; nt < 4; nt++)
                    mma16816(acc[mt][nt], al + 4 * mt, bh + 2 * nt);
        }
    };

    LOAD(0);
    STS(0);
    __syncthreads();
    for (int kt = 0; kt < NKT; kt++) {
        const int buf = kt & 1;
        if (kt + 1 < NKT) LOAD(kt + 1);
        COMPUTE(buf);
        if (kt + 1 < NKT) STS(buf ^ 1);
        __syncthreads();
    }

    // scatter accumulators to padded logits buffer [128][65]
    float* Ls = (float*)(smem + LS_OFF);
    {
        const int r = lane >> 2;
        const int c = 2 * (lane & 3);
#pragma unroll
        for (int mt = 0; mt < 2; mt++)
#pragma unroll
            for (int nt = 0; nt < 4; nt++) {
                const int row = mg + mt * 16 + r;
                const int col = ng + nt * 8 + c;
                Ls[row * 65 + col]           = acc[mt][nt][0];
                Ls[row * 65 + col + 1]       = acc[mt][nt][1];
                Ls[(row + 8) * 65 + col]     = acc[mt][nt][2];
                Ls[(row + 8) * 65 + col + 1] = acc[mt][nt][3];
            }
    }
    __syncthreads();

    // per-token epilogue on threads 0..127
    if (tid < TM) {
        const float* row = Ls + tid * 65;
        float l1 = -1e30f, l2 = -1e30f; int i1 = 0, i2 = 0;
#pragma unroll
        for (int e = 0; e < NE; e++) {
            const float v = row[e];
            if (v > l1)      { l2 = l1; i2 = i1; l1 = v; i1 = e; }
            else if (v > l2) { l2 = v; i2 = e; }
        }
        float s = 0.f;
        float p[NE];
#pragma unroll
        for (int e = 0; e < NE; e++) { p[e] = expf(row[e] - l1); s += p[e]; }
        const float inv_s = 1.f / s;
        const float lse   = l1 + logf(s);

        const float p2   = expf(l2 - l1);
        const float wsum = 1.f + p2;
        const int   gt   = t0 + tid;
        out[2 * gt]                 = 1.f / wsum;
        out[2 * gt + 1]             = p2 / wsum;
        out[2 * N_TOK + 2 * gt]     = (float)i1;
        out[2 * N_TOK + 2 * gt + 1] = (float)i2;

#pragma unroll
        for (int e = 0; e < NE; e++) {
            float v = p[e] * inv_s;
#pragma unroll
            for (int o = 16; o > 0; o >>= 1) v += __shfl_xor_sync(0xffffffffu, v, o);
            if (lane == 0) atomicAdd(&shp[e], v);
        }
        atomicAdd(&shcnt[i1], 1.f);
        atomicAdd(&shcnt[i2], 1.f);
        float zv = lse * lse;
#pragma unroll
        for (int o = 16; o > 0; o >>= 1) zv += __shfl_xor_sync(0xffffffffu, zv, o);
        if (lane == 0) atomicAdd(shz, zv);
    }
    __syncthreads();

    // publish per-block partials
    if (tid < NE) {
        g_Pp[bid * NE + tid] = shp[tid];
        g_cp[bid * NE + tid] = shcnt[tid];
    }
    if (tid == 0) g_zp[bid] = shz[0];
    __threadfence();

    // last CTA to arrive does the deterministic global reduction
    __shared__ unsigned int sLast;
    if (tid == 0) {
        unsigned int r = atomicAdd(&g_arrive, 1u);
        sLast = (r == (unsigned)(gridDim.x - 1)) ? 1u : 0u;
    }
    __syncthreads();
    if (sLast) {
        __threadfence();
        if (tid == 0) shz[0] = 0.f;
        __syncthreads();
        float fp = 0.f;
        if (tid < NE) {
            float sp = 0.f, sc = 0.f;
            for (int b = 0; b < NBLK; b++) {
                sp += g_Pp[b * NE + tid];
                sc += g_cp[b * NE + tid];
            }
            const float f = sc * (1.f / (N_TOK * 2.f));
            const float P = sp * (1.f / N_TOK);
            fp = f * P;
        }
        if (tid >= 128 && tid < 128 + NBLK)
            atomicAdd(shz, g_zp[tid - 128]);
        if (tid < NE) {
#pragma unroll
            for (int o = 16; o > 0; o >>= 1) fp += __shfl_xor_sync(0xffffffffu, fp, o);
            if (lane == 0) shp[wid] = fp;   // shp[0], shp[1]
        }
        __syncthreads();
        if (tid == 0) {
            const float lb = (float)NE * (shp[0] + shp[1]);
            const float z  = shz[0] * (1.f / N_TOK);
            out[4 * N_TOK] = 0.001f * lb + 0.001f * z;
            g_arrive = 0;   // reset for next graph replay
        }
    }
}

extern "C" void kernel_launch(void* const* d_in, const int* in_sizes, int n_in,
                              void* d_out, int out_size)
{
    (void)in_sizes; (void)n_in; (void)out_size;
    const float* X  = (const float*)d_in[0];
    const float* Wg = (const float*)d_in[1];
    float* out = (float*)d_out;

    cudaFuncSetAttribute(router_fused, cudaFuncAttributeMaxDynamicSharedMemorySize, SMEM_TOTAL);
    router_fused<<<NBLK, NTHREADS, SMEM_TOTAL>>>(X, Wg, out);
}